// round 12
// baseline (speedup 1.0000x reference)
#include <cuda_runtime.h>

// Problem shape (fixed by the dataset)
#define TT 4096
#define NB 16
#define CC 512
#define NC (NB * CC)            // 8192 columns
#define TOTAL (TT * NC)         // 33,554,432 floats for new_x

#define CHUNK 64                // rows per thread
#define NCH (TT / CHUNK)        // 64 chunks
#define SUM_BLOCKS ((NCH * NC) / 256)    // 2048
#define RCP_BLOCKS ((TT * NB) / 256)     // 256

// Static scratch (no allocations; fully rewritten every replay — graph-safe)
__device__ float g_agg[NCH * NC];   // 2 MB: per-(chunk, col) sums (L2-resident)
__device__ float g_rcp[TT * NB];    // 256 KB: 1/(t+1+len_n), layout [t][n]

// kA: partial sums in REVERSE chunk order (bid 0 -> chunk 63), so the LOW
// chunks are the last read and stay L2-resident for kB (which reads them
// first). Plus rcp-table role.
__global__ void __launch_bounds__(256)
kA(const float* __restrict__ x, const int* __restrict__ cached_len) {
    int bid = blockIdx.x, tid = threadIdx.x;
    if (bid < SUM_BLOCKS) {
        int idx = bid * 256 + tid;                 // 0 .. NCH*NC-1
        int nc = idx & (NC - 1);
        int chunk = (NCH - 1) - (idx >> 13);       // reversed
        const float* p = x + (size_t)chunk * CHUNK * NC + nc;
        float s = 0.0f;
#pragma unroll 8
        for (int i = 0; i < CHUNK; i++) s += __ldcg(p + (size_t)i * NC);
        g_agg[chunk * NC + nc] = s;
    } else {
        int idx = (bid - SUM_BLOCKS) * 256 + tid;  // 0 .. TT*NB-1
        int n = idx & (NB - 1);
        int t = idx >> 4;
        g_rcp[idx] = 1.0f / ((float)(t + 1) + (float)cached_len[n]);
    }
}

// kB: final scan, chunk-ASCENDING block order (early blocks eat the L2-hot
// low chunks kA just left behind). Base = seed + fold of predecessor chunk
// aggregates (2 MB L2-resident table, independent coalesced loads).
__global__ void __launch_bounds__(256)
kB(const float* __restrict__ x, const int* __restrict__ cached_len,
   const float* __restrict__ cached_avg, float* __restrict__ out, int extras) {
    int idx = blockIdx.x * 256 + threadIdx.x;      // 0 .. NCH*NC-1
    int nc = idx & (NC - 1);
    int chunk = idx >> 13;                         // block-uniform
    int n = nc >> 9;                               // c fastest, C=512

    float run = cached_avg[nc] * (float)cached_len[n];
    const float* pa = g_agg + nc;
#pragma unroll 8
    for (int ch = 0; ch < chunk; ch++) run += pa[(size_t)ch * NC];

    const float* px = x    + (size_t)chunk * CHUNK * NC + nc;
    float*       po = out  + (size_t)chunk * CHUNK * NC + nc;
    const float* pr = g_rcp + (size_t)chunk * CHUNK * NB + n;   // warp-uniform

    float last = 0.0f;
#pragma unroll 8
    for (int i = 0; i < CHUNK; i++) {
        run += __ldcg(px + (size_t)i * NC);
        last = run * pr[(size_t)i * NB];
        __stcs(po + (size_t)i * NC, last);         // evict-first store
    }

    if (extras) {
        // Tuple order: [new_x | new_cached_len (as float) | new_cached_avg]
        if (chunk == NCH - 1) out[TOTAL + NB + nc] = last;      // new_x[T-1]
        if (idx < NB) out[TOTAL + idx] = (float)(cached_len[idx] + TT);
    }
}

extern "C" void kernel_launch(void* const* d_in, const int* in_sizes, int n_in,
                              void* d_out, int out_size) {
    const float* x          = (const float*)d_in[0];   // (T, N, C)
    const int*   cached_len = (const int*)d_in[1];     // (N,)
    const float* cached_avg = (const float*)d_in[2];   // (N, C)
    float* out = (float*)d_out;

    int extras = (out_size >= TOTAL + NB + NC) ? 1 : 0;

    kA<<<SUM_BLOCKS + RCP_BLOCKS, 256>>>(x, cached_len);
    kB<<<SUM_BLOCKS, 256>>>(x, cached_len, cached_avg, out, extras);
}

// round 13
// speedup vs baseline: 1.3861x; 1.3861x over previous
#include <cuda_runtime.h>

// Problem shape (fixed by the dataset)
#define TT 4096
#define NB 16
#define CC 512
#define NC (NB * CC)            // 8192 columns
#define NC4 (NC / 4)            // 2048 float4 columns
#define TOTAL (TT * NC)         // 33,554,432 floats for new_x

#define CHUNK 16                // rows per thread
#define NCH (TT / CHUNK)        // 256 chunks
#define SUM_BLOCKS ((NCH * NC4) / 256)   // 2048
#define RCP_BLOCKS ((TT * NB) / 256)     // 256
#define SCAN_BLOCKS (NC4 / 8)            // 256 (8 warps/block, warp per col4)

// Static scratch (no allocations; fully rewritten every replay — graph-safe)
__device__ float4 g_agg[NCH * NC4];    // 8 MB: per-(chunk, col4) sums
__device__ float4 g_base[NCH * NC4];   // 8 MB: seeded exclusive bases
__device__ float  g_rcp[TT * NB];      // 256 KB: 1/(t+1+len_n), [t][n]

__device__ __forceinline__ float4 f4add(float4 a, float4 b) {
    return make_float4(a.x + b.x, a.y + b.y, a.z + b.z, a.w + b.w);
}
__device__ __forceinline__ float4 f4shfl_up(float4 v, int off) {
    v.x = __shfl_up_sync(0xffffffffu, v.x, off);
    v.y = __shfl_up_sync(0xffffffffu, v.y, off);
    v.z = __shfl_up_sync(0xffffffffu, v.z, off);
    v.w = __shfl_up_sync(0xffffffffu, v.w, off);
    return v;
}

// kA: per-(chunk, col4) partial sums (plain loads) + rcp table role.
__global__ void __launch_bounds__(256)
kA(const float4* __restrict__ x4, const int* __restrict__ cached_len) {
    int bid = blockIdx.x, tid = threadIdx.x;
    if (bid < SUM_BLOCKS) {
        int idx = bid * 256 + tid;                 // 0 .. NCH*NC4-1
        int nc4 = idx & (NC4 - 1);
        int gc = idx >> 11;
        const float4* p = x4 + (size_t)gc * CHUNK * NC4 + nc4;
        float4 s = make_float4(0.f, 0.f, 0.f, 0.f);
#pragma unroll
        for (int i = 0; i < CHUNK; i++) s = f4add(s, p[(size_t)i * NC4]);
        g_agg[gc * NC4 + nc4] = s;
    } else {
        int idx = (bid - SUM_BLOCKS) * 256 + tid;  // 0 .. TT*NB-1
        int n = idx & (NB - 1);
        int t = idx >> 4;
        g_rcp[idx] = 1.0f / ((float)(t + 1) + (float)cached_len[n]);
    }
}

// kscan: warp per col4 column; lane owns 8 consecutive chunks.
// Chain: 8 local adds + 5 shfl steps. Seeds with cached state.
__global__ void __launch_bounds__(256)
kscan(const int* __restrict__ cached_len, const float4* __restrict__ avg4) {
    int col4 = blockIdx.x * 8 + (threadIdx.x >> 5);   // 0 .. NC4-1
    int lane = threadIdx.x & 31;

    float lenf = (float)cached_len[col4 >> 7];
    float4 sa = avg4[col4];
    float4 seed = make_float4(sa.x * lenf, sa.y * lenf, sa.z * lenf, sa.w * lenf);

    // Load my 8 chunk aggregates (independent loads, high MLP).
    float4 a[8];
#pragma unroll
    for (int k = 0; k < 8; k++)
        a[k] = g_agg[(8 * lane + k) * NC4 + col4];

    // Local inclusive total for warp scan.
    float4 tot = a[0];
#pragma unroll
    for (int k = 1; k < 8; k++) tot = f4add(tot, a[k]);

    float4 incl = tot;
#pragma unroll
    for (int off = 1; off < 32; off <<= 1) {
        float4 up = f4shfl_up(incl, off);
        if (lane >= off) incl = f4add(incl, up);
    }
    // Exclusive lane prefix.
    float4 excl = f4shfl_up(incl, 1);
    if (lane == 0) excl = make_float4(0.f, 0.f, 0.f, 0.f);

    // Emit seeded exclusive bases for my 8 chunks.
    float4 run = f4add(seed, excl);
#pragma unroll
    for (int k = 0; k < 8; k++) {
        g_base[(8 * lane + k) * NC4 + col4] = run;
        run = f4add(run, a[k]);
    }
}

// kB: final scan — base is ONE load from g_base (no fold), then plain-load
// streaming of 16 rows, scale by warp-uniform rcp, plain stores.
__global__ void __launch_bounds__(256)
kB(const float4* __restrict__ x4, const int* __restrict__ cached_len,
   float4* __restrict__ out4, int extras) {
    int idx = blockIdx.x * 256 + threadIdx.x;      // 0 .. NCH*NC4-1
    int nc4 = idx & (NC4 - 1);
    int gc = idx >> 11;                            // block-uniform
    int n = nc4 >> 7;                              // warp-uniform

    float4 run = g_base[gc * NC4 + nc4];
    const float4* px = x4   + (size_t)gc * CHUNK * NC4 + nc4;
    float4*       po = out4 + (size_t)gc * CHUNK * NC4 + nc4;
    const float*  pr = g_rcp + (size_t)gc * CHUNK * NB + n;

    float4 last = make_float4(0.f, 0.f, 0.f, 0.f);
#pragma unroll
    for (int i = 0; i < CHUNK; i++) {
        float4 v = px[(size_t)i * NC4];
        run = f4add(run, v);
        float r = pr[(size_t)i * NB];
        last.x = run.x * r; last.y = run.y * r;
        last.z = run.z * r; last.w = run.w * r;
        po[(size_t)i * NC4] = last;
    }

    if (extras) {
        // Tuple order: [new_x | new_cached_len (as float) | new_cached_avg]
        if (gc == NCH - 1)
            out4[(TOTAL + NB) / 4 + nc4] = last;   // new_x[T-1]
        if (idx < NB) {
            float* outf = (float*)out4;
            outf[TOTAL + idx] = (float)(cached_len[idx] + TT);
        }
    }
}

extern "C" void kernel_launch(void* const* d_in, const int* in_sizes, int n_in,
                              void* d_out, int out_size) {
    const float4* x4         = (const float4*)d_in[0];   // (T, N, C)
    const int*    cached_len = (const int*)d_in[1];      // (N,)
    const float4* avg4       = (const float4*)d_in[2];   // (N, C)
    float4* out4 = (float4*)d_out;

    int extras = (out_size >= TOTAL + NB + NC) ? 1 : 0;

    kA<<<SUM_BLOCKS + RCP_BLOCKS, 256>>>(x4, cached_len);
    kscan<<<SCAN_BLOCKS, 256>>>(cached_len, avg4);
    kB<<<SUM_BLOCKS, 256>>>(x4, cached_len, out4, extras);
}